// round 1
// baseline (speedup 1.0000x reference)
#include <cuda_runtime.h>

// ---------------------------------------------------------------------------
// PatchCRPS:  mean( (sort(unfold9(pred - avg9(pred))) -
//                    sort(unfold9(targ - avg9(targ))))^2 )
// Shapes: (8,1,256,256) fp32.  K=9, P=4, count_include_pad=False.
// ---------------------------------------------------------------------------

#define B 8
#define H 256
#define W 256
#define NPIX (B * H * W)           // 524288
#define NBLK (NPIX / 128)          // 4096 main-kernel blocks
#define NTOT 42467328.0            // B*H*W*81

// Scratch (device globals — no allocation)
__device__ float  g_tmp[2][NPIX];      // horizontal box sums
__device__ float  g_dist[2][NPIX];     // x - avgpool9(x)
__device__ float  g_partial[NBLK];     // per-block partial sums

// ---------------------------------------------------------------------------
// Pass 1: horizontal valid-window sum (9 wide)
// ---------------------------------------------------------------------------
__global__ void hsum_kernel(const float* __restrict__ pred,
                            const float* __restrict__ targ) {
    int idx = blockIdx.x * 256 + threadIdx.x;   // 0 .. 2*NPIX-1
    int t   = idx >> 19;                        // 0=pred, 1=targ
    int pix = idx & (NPIX - 1);
    const float* __restrict__ src = t ? targ : pred;
    int w    = pix & 255;
    int base = pix - w;
    float s = 0.f;
#pragma unroll
    for (int dx = -4; dx <= 4; dx++) {
        int ww = w + dx;
        if ((unsigned)ww < 256u) s += src[base + ww];
    }
    g_tmp[t][pix] = s;
}

// ---------------------------------------------------------------------------
// Pass 2: vertical valid-window sum + divide by valid count + subtract
// ---------------------------------------------------------------------------
__global__ void vdist_kernel(const float* __restrict__ pred,
                             const float* __restrict__ targ) {
    int idx = blockIdx.x * 256 + threadIdx.x;
    int t   = idx >> 19;
    int pix = idx & (NPIX - 1);
    int w = pix & 255;
    int h = (pix >> 8) & 255;
    float s = 0.f;
#pragma unroll
    for (int dy = -4; dy <= 4; dy++) {
        int hh = h + dy;
        if ((unsigned)hh < 256u) s += g_tmp[t][pix + dy * 256];
    }
    int ch = min(h + 4, 255) - max(h - 4, 0) + 1;
    int cw = min(w + 4, 255) - max(w - 4, 0) + 1;
    const float* __restrict__ src = t ? targ : pred;
    g_dist[t][pix] = src[pix] - s / (float)(ch * cw);
}

// ---------------------------------------------------------------------------
// Sorting network: Batcher odd-even mergesort for n=128, pruned to 81 wires.
// CEs touching index >= 81 are skipped (virtual +inf pad: min(x,inf)=x at the
// low wire, inf never descends -> pruned network sorts the first 81 wires).
// Fully unrolled: all indices compile-time constants -> v[] stays in registers.
// ---------------------------------------------------------------------------
__device__ __forceinline__ void sort81(float v[81]) {
#pragma unroll
    for (int p = 1; p < 128; p <<= 1) {
#pragma unroll
        for (int k = p; k >= 1; k >>= 1) {
#pragma unroll
            for (int j = k % p; j + k < 128; j += 2 * k) {
#pragma unroll
                for (int i = 0; i < k; i++) {
                    int lo = i + j, hi = i + j + k;
                    if (hi < 81 && (lo / (2 * p)) == (hi / (2 * p))) {
                        float a = v[lo], b = v[hi];
                        v[lo] = fminf(a, b);
                        v[hi] = fmaxf(a, b);
                    }
                }
            }
        }
    }
}

// ---------------------------------------------------------------------------
// Main kernel: one thread per pixel.
//   load 81-patch of pred_dist -> sort in regs -> stash to SMEM
//   load 81-patch of targ_dist -> sort in regs -> diff vs SMEM -> accumulate
// ---------------------------------------------------------------------------
__global__ __launch_bounds__(128) void patchcrps_kernel() {
    __shared__ float s[81 * 128];   // per-thread sorted pred (conflict-free)
    __shared__ float ws[4];

    int tid  = threadIdx.x;
    int pix  = blockIdx.x * 128 + tid;
    int w    = pix & 255;
    int h    = (pix >> 8) & 255;
    int base = pix & ~65535;        // image base (b * 65536)

    float v[81];

    // ---- prediction patch ----
#pragma unroll
    for (int dy = -4; dy <= 4; dy++) {
        int hh = h + dy;
        bool hv = (unsigned)hh < 256u;
#pragma unroll
        for (int dx = -4; dx <= 4; dx++) {
            int ww = w + dx;
            float x = 0.f;
            if (hv && (unsigned)ww < 256u) x = g_dist[0][base + hh * 256 + ww];
            v[(dy + 4) * 9 + (dx + 4)] = x;
        }
    }
    sort81(v);
#pragma unroll
    for (int i = 0; i < 81; i++) s[i * 128 + tid] = v[i];

    // ---- target patch ----
#pragma unroll
    for (int dy = -4; dy <= 4; dy++) {
        int hh = h + dy;
        bool hv = (unsigned)hh < 256u;
#pragma unroll
        for (int dx = -4; dx <= 4; dx++) {
            int ww = w + dx;
            float x = 0.f;
            if (hv && (unsigned)ww < 256u) x = g_dist[1][base + hh * 256 + ww];
            v[(dy + 4) * 9 + (dx + 4)] = x;
        }
    }
    sort81(v);

    float acc = 0.f;
#pragma unroll
    for (int i = 0; i < 81; i++) {
        float d = v[i] - s[i * 128 + tid];
        acc += d * d;
    }

    // ---- block reduction (deterministic; partials to global) ----
#pragma unroll
    for (int off = 16; off; off >>= 1)
        acc += __shfl_xor_sync(0xffffffffu, acc, off);
    if ((tid & 31) == 0) ws[tid >> 5] = acc;
    __syncthreads();
    if (tid == 0) g_partial[blockIdx.x] = ws[0] + ws[1] + ws[2] + ws[3];
}

// ---------------------------------------------------------------------------
// Final deterministic reduction in double
// ---------------------------------------------------------------------------
__global__ void finalize_kernel(float* __restrict__ out) {
    __shared__ double sh[256];
    int tid = threadIdx.x;
    double s = 0.0;
    for (int i = tid; i < NBLK; i += 256) s += (double)g_partial[i];
    sh[tid] = s;
    __syncthreads();
    for (int off = 128; off; off >>= 1) {
        if (tid < off) sh[tid] += sh[tid + off];
        __syncthreads();
    }
    if (tid == 0) out[0] = (float)(sh[0] / NTOT);
}

// ---------------------------------------------------------------------------
extern "C" void kernel_launch(void* const* d_in, const int* in_sizes, int n_in,
                              void* d_out, int out_size) {
    const float* pred = (const float*)d_in[0];
    const float* targ = (const float*)d_in[1];
    float* out = (float*)d_out;

    hsum_kernel<<<2 * NPIX / 256, 256>>>(pred, targ);
    vdist_kernel<<<2 * NPIX / 256, 256>>>(pred, targ);
    patchcrps_kernel<<<NBLK, 128>>>();
    finalize_kernel<<<1, 256>>>(out);
}

// round 3
// speedup vs baseline: 1.0758x; 1.0758x over previous
#include <cuda_runtime.h>

// ---------------------------------------------------------------------------
// PatchCRPS:  mean( (sort(unfold9(pred - avg9(pred))) -
//                    sort(unfold9(targ - avg9(targ))))^2 )
// Shapes: (8,1,256,256) fp32.  K=9, P=4, count_include_pad=False.
//
// R3 = R2 resubmit (R2 never ran: infra failure).
// Pair-thread sort (even lane = pred, odd lane = targ, same pixel),
// no SMEM stash, regs capped via __launch_bounds__(256,2) -> no spills.
// Finalize fused into main kernel (last-block-done pattern).
// ---------------------------------------------------------------------------

#define B 8
#define H 256
#define W 256
#define NPIX (B * H * W)           // 524288
#define NBLK (NPIX / 128)          // 4096 main-kernel blocks (128 pixels each)
#define NTOT 42467328.0            // B*H*W*81

// Scratch (device globals — no allocation)
__device__ float    g_tmp[2][NPIX];      // horizontal box sums
__device__ float    g_dist[2][NPIX];     // x - avgpool9(x)
__device__ float    g_partial[NBLK];     // per-block partial sums
__device__ unsigned g_count;             // last-block-done counter

// ---------------------------------------------------------------------------
// Pass 1: horizontal valid-window sum (9 wide). Also resets g_count.
// ---------------------------------------------------------------------------
__global__ void hsum_kernel(const float* __restrict__ pred,
                            const float* __restrict__ targ) {
    if (blockIdx.x == 0 && threadIdx.x == 0) g_count = 0u;
    int idx = blockIdx.x * 256 + threadIdx.x;   // 0 .. 2*NPIX-1
    int t   = idx >> 19;                        // 0=pred, 1=targ
    int pix = idx & (NPIX - 1);
    const float* __restrict__ src = t ? targ : pred;
    int w    = pix & 255;
    int base = pix - w;
    float s = 0.f;
#pragma unroll
    for (int dx = -4; dx <= 4; dx++) {
        int ww = w + dx;
        if ((unsigned)ww < 256u) s += src[base + ww];
    }
    g_tmp[t][pix] = s;
}

// ---------------------------------------------------------------------------
// Pass 2: vertical valid-window sum + divide by valid count + subtract
// ---------------------------------------------------------------------------
__global__ void vdist_kernel(const float* __restrict__ pred,
                             const float* __restrict__ targ) {
    int idx = blockIdx.x * 256 + threadIdx.x;
    int t   = idx >> 19;
    int pix = idx & (NPIX - 1);
    int w = pix & 255;
    int h = (pix >> 8) & 255;
    float s = 0.f;
#pragma unroll
    for (int dy = -4; dy <= 4; dy++) {
        int hh = h + dy;
        if ((unsigned)hh < 256u) s += g_tmp[t][pix + dy * 256];
    }
    int ch = min(h + 4, 255) - max(h - 4, 0) + 1;
    int cw = min(w + 4, 255) - max(w - 4, 0) + 1;
    const float* __restrict__ src = t ? targ : pred;
    g_dist[t][pix] = src[pix] - s / (float)(ch * cw);
}

// ---------------------------------------------------------------------------
// Sorting network: Batcher odd-even mergesort for n=128, pruned to 81 wires.
// Wires >= 81 hold virtual +inf: any CE with hi >= 81 is a no-op (min(x,inf)=x,
// inf never descends) -> pruned. Fully unrolled, constant indices -> registers.
// ---------------------------------------------------------------------------
__device__ __forceinline__ void sort81(float v[81]) {
#pragma unroll
    for (int p = 1; p < 128; p <<= 1) {
#pragma unroll
        for (int k = p; k >= 1; k >>= 1) {
#pragma unroll
            for (int j = k % p; j + k < 128; j += 2 * k) {
#pragma unroll
                for (int i = 0; i < k; i++) {
                    int lo = i + j, hi = i + j + k;
                    if (hi < 81 && (lo / (2 * p)) == (hi / (2 * p))) {
                        float a = v[lo], b = v[hi];
                        v[lo] = fminf(a, b);
                        v[hi] = fmaxf(a, b);
                    }
                }
            }
        }
    }
}

// ---------------------------------------------------------------------------
// Main kernel: 256 threads, 128 pixels/block. Lane pair (2t, 2t+1) handles one
// pixel: even lane sorts pred patch, odd lane sorts targ patch. Sorted diff via
// __shfl_xor(.,1); both lanes accumulate the same d^2 -> divide total by 2.
// Last block performs the deterministic final reduction (fixed order, double).
// ---------------------------------------------------------------------------
__global__ __launch_bounds__(256, 2) void patchcrps_kernel(float* __restrict__ out) {
    int tid  = threadIdx.x;
    int t    = tid & 1;                       // 0=pred, 1=targ
    int pix  = blockIdx.x * 128 + (tid >> 1);
    int w    = pix & 255;
    int h    = (pix >> 8) & 255;
    int base = pix & ~65535;                  // image base (b * 65536)

    const float* __restrict__ src = g_dist[t];

    float v[81];
#pragma unroll
    for (int dy = -4; dy <= 4; dy++) {
        int hh = h + dy;
        bool hv = (unsigned)hh < 256u;
#pragma unroll
        for (int dx = -4; dx <= 4; dx++) {
            int ww = w + dx;
            float x = 0.f;
            if (hv && (unsigned)ww < 256u) x = src[base + hh * 256 + ww];
            v[(dy + 4) * 9 + (dx + 4)] = x;
        }
    }

    sort81(v);

    float acc = 0.f;
#pragma unroll
    for (int i = 0; i < 81; i++) {
        float o = __shfl_xor_sync(0xffffffffu, v[i], 1);
        float d = v[i] - o;
        acc += d * d;
    }

    // ---- block reduction (deterministic) ----
#pragma unroll
    for (int off = 16; off; off >>= 1)
        acc += __shfl_xor_sync(0xffffffffu, acc, off);

    __shared__ float ws[8];
    __shared__ bool  isLast;
    if ((tid & 31) == 0) ws[tid >> 5] = acc;
    __syncthreads();
    if (tid == 0) {
        float s = 0.f;
#pragma unroll
        for (int k = 0; k < 8; k++) s += ws[k];
        g_partial[blockIdx.x] = s;
        __threadfence();
        unsigned c = atomicAdd(&g_count, 1u);
        isLast = (c == NBLK - 1);
    }
    __syncthreads();

    // ---- fused finalize: last block, fixed-order double reduction ----
    if (isLast) {
        __shared__ double sh[256];
        double s = 0.0;
        for (int i = tid; i < NBLK; i += 256) s += (double)g_partial[i];
        sh[tid] = s;
        __syncthreads();
        for (int off = 128; off; off >>= 1) {
            if (tid < off) sh[tid] += sh[tid + off];
            __syncthreads();
        }
        if (tid == 0) out[0] = (float)(sh[0] / (2.0 * NTOT));
    }
}

// ---------------------------------------------------------------------------
extern "C" void kernel_launch(void* const* d_in, const int* in_sizes, int n_in,
                              void* d_out, int out_size) {
    const float* pred = (const float*)d_in[0];
    const float* targ = (const float*)d_in[1];
    float* out = (float*)d_out;

    hsum_kernel<<<2 * NPIX / 256, 256>>>(pred, targ);
    vdist_kernel<<<2 * NPIX / 256, 256>>>(pred, targ);
    patchcrps_kernel<<<NBLK, 256>>>(out);
}

// round 4
// speedup vs baseline: 5.7809x; 5.3736x over previous
#include <cuda_runtime.h>

// ---------------------------------------------------------------------------
// PatchCRPS:  mean( (sort(unfold9(pred - avg9(pred))) -
//                    sort(unfold9(targ - avg9(targ))))^2 )
// Shapes: (8,1,256,256) fp32.  K=9, P=4, count_include_pad=False.
//
// R4: sorting network emitted via constexpr CE table + template recursion ->
// every index compile-time constant -> v[81] provably register-resident
// (R1/R3 suspicion: nested #pragma unroll silently failed -> local memory).
// ---------------------------------------------------------------------------

#define B 8
#define H 256
#define W 256
#define NPIX (B * H * W)           // 524288
#define NBLK (NPIX / 128)          // 4096 main-kernel blocks (128 pixels each)
#define NTOT 42467328.0            // B*H*W*81

// Scratch (device globals — no allocation)
__device__ float    g_tmp[2][NPIX];      // horizontal box sums
__device__ float    g_dist[2][NPIX];     // x - avgpool9(x)
__device__ float    g_partial[NBLK];     // per-block partial sums
__device__ unsigned g_count;             // last-block-done counter

// ---------------------------------------------------------------------------
// Compile-time pruned Batcher odd-even mergesort network (n=128, wires<81).
// Wires >= 81 hold virtual +inf: CEs with hi >= 81 are no-ops -> pruned.
// ---------------------------------------------------------------------------
struct Net {
    int lo[1024];
    int hi[1024];
    int n;
    constexpr Net() : lo(), hi(), n(0) {
        for (int p = 1; p < 128; p <<= 1)
            for (int k = p; k >= 1; k >>= 1)
                for (int j = k % p; j + k < 128; j += 2 * k)
                    for (int i = 0; i < k; i++) {
                        int a = i + j, b = i + j + k;
                        if (b < 81 && (a / (2 * p)) == (b / (2 * p))) {
                            lo[n] = a; hi[n] = b; n++;
                        }
                    }
    }
};
__device__ constexpr Net NET;

template <int I, int T>
__device__ __forceinline__ void applyChunk(float (&v)[81]) {
    if constexpr (T > 0 && I < NET.n) {
        constexpr int a = NET.lo[I];
        constexpr int b = NET.hi[I];
        float x = v[a], y = v[b];
        v[a] = fminf(x, y);
        v[b] = fmaxf(x, y);
        applyChunk<I + 1, T - 1>(v);
    }
}

template <int I>
__device__ __forceinline__ void applyAll(float (&v)[81]) {
    if constexpr (I < NET.n) {
        applyChunk<I, 32>(v);
        applyAll<I + 32>(v);
    }
}

__device__ __forceinline__ void sort81(float (&v)[81]) { applyAll<0>(v); }

// ---------------------------------------------------------------------------
// Pass 1: horizontal valid-window sum (9 wide). Also resets g_count.
// ---------------------------------------------------------------------------
__global__ void hsum_kernel(const float* __restrict__ pred,
                            const float* __restrict__ targ) {
    if (blockIdx.x == 0 && threadIdx.x == 0) g_count = 0u;
    int idx = blockIdx.x * 256 + threadIdx.x;   // 0 .. 2*NPIX-1
    int t   = idx >> 19;                        // 0=pred, 1=targ
    int pix = idx & (NPIX - 1);
    const float* __restrict__ src = t ? targ : pred;
    int w    = pix & 255;
    int base = pix - w;
    float s = 0.f;
#pragma unroll
    for (int dx = -4; dx <= 4; dx++) {
        int ww = w + dx;
        if ((unsigned)ww < 256u) s += src[base + ww];
    }
    g_tmp[t][pix] = s;
}

// ---------------------------------------------------------------------------
// Pass 2: vertical valid-window sum + divide by valid count + subtract
// ---------------------------------------------------------------------------
__global__ void vdist_kernel(const float* __restrict__ pred,
                             const float* __restrict__ targ) {
    int idx = blockIdx.x * 256 + threadIdx.x;
    int t   = idx >> 19;
    int pix = idx & (NPIX - 1);
    int w = pix & 255;
    int h = (pix >> 8) & 255;
    float s = 0.f;
#pragma unroll
    for (int dy = -4; dy <= 4; dy++) {
        int hh = h + dy;
        if ((unsigned)hh < 256u) s += g_tmp[t][pix + dy * 256];
    }
    int ch = min(h + 4, 255) - max(h - 4, 0) + 1;
    int cw = min(w + 4, 255) - max(w - 4, 0) + 1;
    const float* __restrict__ src = t ? targ : pred;
    g_dist[t][pix] = src[pix] - s / (float)(ch * cw);
}

// ---------------------------------------------------------------------------
// Main kernel: 256 threads, 128 pixels/block. Lane pair (2t, 2t+1) handles one
// pixel: even lane sorts pred patch, odd lane sorts targ patch. Sorted diff via
// __shfl_xor(.,1); both lanes accumulate the same d^2 -> divide total by 2.
// Last block performs the deterministic final reduction (fixed order, double).
// ---------------------------------------------------------------------------
__global__ __launch_bounds__(256, 1) void patchcrps_kernel(float* __restrict__ out) {
    int tid  = threadIdx.x;
    int t    = tid & 1;                       // 0=pred, 1=targ
    int pix  = blockIdx.x * 128 + (tid >> 1);
    int w    = pix & 255;
    int h    = (pix >> 8) & 255;
    int base = pix & ~65535;                  // image base (b * 65536)

    const float* __restrict__ src = g_dist[t];

    float v[81];
#pragma unroll
    for (int dy = -4; dy <= 4; dy++) {
        int hh = h + dy;
        bool hv = (unsigned)hh < 256u;
#pragma unroll
        for (int dx = -4; dx <= 4; dx++) {
            int ww = w + dx;
            float x = 0.f;
            if (hv && (unsigned)ww < 256u) x = src[base + hh * 256 + ww];
            v[(dy + 4) * 9 + (dx + 4)] = x;
        }
    }

    sort81(v);

    float acc = 0.f;
#pragma unroll
    for (int i = 0; i < 81; i++) {
        float o = __shfl_xor_sync(0xffffffffu, v[i], 1);
        float d = v[i] - o;
        acc += d * d;
    }

    // ---- block reduction (deterministic) ----
#pragma unroll
    for (int off = 16; off; off >>= 1)
        acc += __shfl_xor_sync(0xffffffffu, acc, off);

    __shared__ float ws[8];
    __shared__ bool  isLast;
    if ((tid & 31) == 0) ws[tid >> 5] = acc;
    __syncthreads();
    if (tid == 0) {
        float s = 0.f;
#pragma unroll
        for (int k = 0; k < 8; k++) s += ws[k];
        g_partial[blockIdx.x] = s;
        __threadfence();
        unsigned c = atomicAdd(&g_count, 1u);
        isLast = (c == NBLK - 1);
    }
    __syncthreads();

    // ---- fused finalize: last block, fixed-order double reduction ----
    if (isLast) {
        __shared__ double sh[256];
        double s = 0.0;
        for (int i = tid; i < NBLK; i += 256) s += (double)g_partial[i];
        sh[tid] = s;
        __syncthreads();
        for (int off = 128; off; off >>= 1) {
            if (tid < off) sh[tid] += sh[tid + off];
            __syncthreads();
        }
        if (tid == 0) out[0] = (float)(sh[0] / (2.0 * NTOT));
    }
}

// Trailing no-op: pads the per-call launch count to 4 so ncu's skip window
// (observed to land on launch #7) falls on patchcrps_kernel next capture.
__global__ void pad_kernel() {}

// ---------------------------------------------------------------------------
extern "C" void kernel_launch(void* const* d_in, const int* in_sizes, int n_in,
                              void* d_out, int out_size) {
    const float* pred = (const float*)d_in[0];
    const float* targ = (const float*)d_in[1];
    float* out = (float*)d_out;

    hsum_kernel<<<2 * NPIX / 256, 256>>>(pred, targ);
    vdist_kernel<<<2 * NPIX / 256, 256>>>(pred, targ);
    patchcrps_kernel<<<NBLK, 256>>>(out);
    pad_kernel<<<1, 32>>>();
}

// round 5
// speedup vs baseline: 6.3063x; 1.0909x over previous
#include <cuda_runtime.h>

// ---------------------------------------------------------------------------
// PatchCRPS:  mean( (sort(unfold9(pred - avg9(pred))) -
//                    sort(unfold9(targ - avg9(targ))))^2 )
// Shapes: (8,1,256,256) fp32.  K=9, P=4, count_include_pad=False.
//
// R5: shared-column merge sort. Block = one image row (both tensors).
// Each thread sorts ONE column of 9 (shared by 9 pixels via SMEM), then
// merges 9 pre-sorted columns with the merge phases of a 256-wire Batcher
// network (columns at 16-wire spacing, +inf padded), pruned exactly by a
// constexpr always-inf simulation. ~830 CEs/pixel vs 1471 for full sort.
// ---------------------------------------------------------------------------

#define B 8
#define H 256
#define W 256
#define NPIX (B * H * W)           // 524288
#define NROW (B * H)               // 2048 main-kernel blocks (1 row each)
#define NTOT 42467328.0            // B*H*W*81

// Scratch (device globals — no allocation)
__device__ float    g_tmp[2][NPIX];      // horizontal box sums
__device__ float    g_dist[2][NPIX];     // x - avgpool9(x)
__device__ float    g_partial[NROW];     // per-block partial sums
__device__ unsigned g_count;             // last-block-done counter

// ---------------------------------------------------------------------------
// Column sorter: Batcher network for n=16 pruned to 9 wires (wires>=9 = +inf).
// ---------------------------------------------------------------------------
struct Net9 {
    int lo[64]; int hi[64]; int n;
    constexpr Net9() : lo(), hi(), n(0) {
        for (int p = 1; p < 16; p <<= 1)
            for (int k = p; k >= 1; k >>= 1)
                for (int j = k % p; j + k < 16; j += 2 * k)
                    for (int i = 0; i < k; i++) {
                        int a = i + j, b = i + j + k;
                        if (b < 9 && (a / (2 * p)) == (b / (2 * p))) {
                            lo[n] = a; hi[n] = b; n++;
                        }
                    }
    }
};
__device__ constexpr Net9 N9;

template <int I>
__device__ __forceinline__ void apply9(float (&v)[9]) {
    if constexpr (I < N9.n) {
        constexpr int a = N9.lo[I];
        constexpr int b = N9.hi[I];
        float x = v[a], y = v[b];
        v[a] = fminf(x, y);
        v[b] = fmaxf(x, y);
        apply9<I + 1>(v);
    }
}
__device__ __forceinline__ void sort9(float (&v)[9]) { apply9<0>(v); }

// ---------------------------------------------------------------------------
// Merge network: 256-wire Batcher, phases p>=16 only (16-blocks pre-sorted:
// each block = sorted column of 9 + 7x +inf pad; columns 9..15 all +inf).
// Exact pruning via constexpr always-inf simulation:
//   b always-inf              -> op is a no-op            -> pruned
//   a always-inf, b finite    -> (min,max)=(v_b, inf)     -> MOV a<-b
//   else                      -> compare-exchange
// Pad wires are never READ before being written -> no init needed.
// Finite results end in wires 0..80, sorted ascending.
// ---------------------------------------------------------------------------
struct MergeNet {
    short a[2048]; short b[2048]; short mv[2048]; int n;
    constexpr MergeNet() : a(), b(), mv(), n(0) {
        bool inf[256] = {};
        for (int c = 0; c < 16; c++)
            for (int i = 0; i < 16; i++)
                inf[c * 16 + i] = (c >= 9) || (i >= 9);
        for (int p = 16; p < 256; p <<= 1)
            for (int k = p; k >= 1; k >>= 1)
                for (int j = k % p; j + k < 256; j += 2 * k)
                    for (int i = 0; i < k; i++) {
                        int x = i + j, y = i + j + k;
                        if ((x / (2 * p)) != (y / (2 * p))) continue;
                        if (inf[y]) continue;              // no-op
                        if (inf[x]) {                       // MOV x<-y
                            a[n] = (short)x; b[n] = (short)y; mv[n] = 1; n++;
                            inf[x] = false; inf[y] = true;
                        } else {
                            a[n] = (short)x; b[n] = (short)y; mv[n] = 0; n++;
                        }
                    }
    }
};
__device__ constexpr MergeNet MN;

template <int I, int T>
__device__ __forceinline__ void mergeChunk(float (&v)[144]) {
    if constexpr (T > 0 && I < MN.n) {
        constexpr int x = MN.a[I];
        constexpr int y = MN.b[I];
        if constexpr (MN.mv[I] != 0) {
            v[x] = v[y];
        } else {
            float p = v[x], q = v[y];
            v[x] = fminf(p, q);
            v[y] = fmaxf(p, q);
        }
        mergeChunk<I + 1, T - 1>(v);
    }
}
template <int I>
__device__ __forceinline__ void mergeAll(float (&v)[144]) {
    if constexpr (I < MN.n) {
        mergeChunk<I, 32>(v);
        mergeAll<I + 32>(v);
    }
}
__device__ __forceinline__ void merge81(float (&v)[144]) { mergeAll<0>(v); }

// ---------------------------------------------------------------------------
// Pass 1: horizontal valid-window sum (9 wide). Also resets g_count.
// ---------------------------------------------------------------------------
__global__ void hsum_kernel(const float* __restrict__ pred,
                            const float* __restrict__ targ) {
    if (blockIdx.x == 0 && threadIdx.x == 0) g_count = 0u;
    int idx = blockIdx.x * 256 + threadIdx.x;
    int t   = idx >> 19;
    int pix = idx & (NPIX - 1);
    const float* __restrict__ src = t ? targ : pred;
    int w    = pix & 255;
    int base = pix - w;
    float s = 0.f;
#pragma unroll
    for (int dx = -4; dx <= 4; dx++) {
        int ww = w + dx;
        if ((unsigned)ww < 256u) s += src[base + ww];
    }
    g_tmp[t][pix] = s;
}

// ---------------------------------------------------------------------------
// Pass 2: vertical valid-window sum + divide by valid count + subtract
// ---------------------------------------------------------------------------
__global__ void vdist_kernel(const float* __restrict__ pred,
                             const float* __restrict__ targ) {
    int idx = blockIdx.x * 256 + threadIdx.x;
    int t   = idx >> 19;
    int pix = idx & (NPIX - 1);
    int w = pix & 255;
    int h = (pix >> 8) & 255;
    float s = 0.f;
#pragma unroll
    for (int dy = -4; dy <= 4; dy++) {
        int hh = h + dy;
        if ((unsigned)hh < 256u) s += g_tmp[t][pix + dy * 256];
    }
    int ch = min(h + 4, 255) - max(h - 4, 0) + 1;
    int cw = min(w + 4, 255) - max(w - 4, 0) + 1;
    const float* __restrict__ src = t ? targ : pred;
    g_dist[t][pix] = src[pix] - s / (float)(ch * cw);
}

// ---------------------------------------------------------------------------
// Main kernel: block = one (batch,row). 512 threads: 0-255 pred / 256-511 targ,
// thread column w. Sort own column -> SMEM -> gather 9 sorted columns ->
// merge network -> sorted diff via SMEM chunk exchange -> reduce.
// ---------------------------------------------------------------------------
__global__ __launch_bounds__(512, 1) void patchcrps_kernel(float* __restrict__ out) {
    __shared__ float scol[2][9][264];    // sorted columns, 4 zero pad each side
    __shared__ float ex[256][19];        // diff-exchange chunks (pad: no conflicts)
    __shared__ float ws[16];
    __shared__ bool  isLast;

    int tid = threadIdx.x;
    int t   = tid >> 8;                  // 0=pred, 1=targ
    int w   = tid & 255;
    int b   = blockIdx.x >> 8;
    int h   = blockIdx.x & 255;
    int base = b * 65536 + w;

    const float* __restrict__ src = g_dist[t];

    // ---- 1. load + sort own column (rows h-4..h+4 at column w) ----
    float col[9];
#pragma unroll
    for (int i = 0; i < 9; i++) {
        int hh = h - 4 + i;
        col[i] = ((unsigned)hh < 256u) ? src[base + hh * 256] : 0.f;
    }
    sort9(col);

    // ---- 2. publish column (+ zero the 4-wide pads) ----
#pragma unroll
    for (int i = 0; i < 9; i++) {
        scol[t][i][w + 4] = col[i];
        if (w < 4) { scol[t][i][w] = 0.f; scol[t][i][260 + w] = 0.f; }
    }
    __syncthreads();

    // ---- 3. gather 9 sorted columns into 16-spaced wires ----
    float v[144];
#pragma unroll
    for (int dx = 0; dx < 9; dx++)
#pragma unroll
        for (int i = 0; i < 9; i++)
            v[dx * 16 + i] = scol[t][i][w + dx];

    // ---- 4. merge: sorted 81 ends in wires 0..80 ----
    merge81(v);

    // ---- 5. sorted diff via chunked SMEM exchange (targ -> pred) ----
    float acc = 0.f;
#pragma unroll
    for (int c0 = 0; c0 < 81; c0 += 18) {
        if (t == 1) {
#pragma unroll
            for (int e = 0; e < 18; e++)
                if (c0 + e < 81) ex[w][e] = v[c0 + e];
        }
        __syncthreads();
        if (t == 0) {
#pragma unroll
            for (int e = 0; e < 18; e++)
                if (c0 + e < 81) {
                    float d = v[c0 + e] - ex[w][e];
                    acc += d * d;
                }
        }
        __syncthreads();
    }

    // ---- 6. block reduction (deterministic) ----
#pragma unroll
    for (int off = 16; off; off >>= 1)
        acc += __shfl_xor_sync(0xffffffffu, acc, off);
    if ((tid & 31) == 0) ws[tid >> 5] = acc;
    __syncthreads();
    if (tid == 0) {
        float s = 0.f;
#pragma unroll
        for (int k = 0; k < 16; k++) s += ws[k];
        g_partial[blockIdx.x] = s;
        __threadfence();
        unsigned c = atomicAdd(&g_count, 1u);
        isLast = (c == NROW - 1);
    }
    __syncthreads();

    // ---- 7. fused finalize: last block, fixed-order double reduction ----
    if (isLast) {
        __shared__ double sh[512];
        double s = 0.0;
        for (int i = tid; i < NROW; i += 512) s += (double)g_partial[i];
        sh[tid] = s;
        __syncthreads();
        for (int off = 256; off; off >>= 1) {
            if (tid < off) sh[tid] += sh[tid + off];
            __syncthreads();
        }
        if (tid == 0) out[0] = (float)(sh[0] / NTOT);
    }
}

// ---------------------------------------------------------------------------
extern "C" void kernel_launch(void* const* d_in, const int* in_sizes, int n_in,
                              void* d_out, int out_size) {
    const float* pred = (const float*)d_in[0];
    const float* targ = (const float*)d_in[1];
    float* out = (float*)d_out;

    hsum_kernel<<<2 * NPIX / 256, 256>>>(pred, targ);
    vdist_kernel<<<2 * NPIX / 256, 256>>>(pred, targ);
    patchcrps_kernel<<<NROW, 512>>>(out);
}

// round 6
// speedup vs baseline: 6.9785x; 1.1066x over previous
#include <cuda_runtime.h>

// ---------------------------------------------------------------------------
// PatchCRPS:  mean( (sort(unfold9(pred - avg9(pred))) -
//                    sort(unfold9(targ - avg9(targ))))^2 )
// Shapes: (8,1,256,256) fp32.  K=9, P=4, count_include_pad=False.
//
// R6: column-sort + merge (as R5) but 256 threads/block so the 255-reg budget
// holds v[144] in registers (R5 ran 512 thr -> 126-reg cap -> spilled).
// Pair-thread layout (even lane = pred, odd = targ) -> shuffle diff, no SMEM
// exchange. scol interleaved [i][2c+t] -> conflict-free publish & gather.
// ---------------------------------------------------------------------------

#define B 8
#define H 256
#define W 256
#define NPIX (B * H * W)           // 524288
#define NBLKM (2 * B * H)          // 4096 main blocks (half-row each)
#define NTOT 42467328.0            // B*H*W*81

// Scratch (device globals — no allocation)
__device__ float    g_tmp[2][NPIX];      // horizontal box sums
__device__ float    g_dist[2][NPIX];     // x - avgpool9(x)
__device__ float    g_partial[NBLKM];    // per-block partial sums
__device__ unsigned g_count;             // last-block-done counter

// ---------------------------------------------------------------------------
// Column sorter: Batcher network for n=16 pruned to 9 wires (wires>=9 = +inf).
// ---------------------------------------------------------------------------
struct Net9 {
    int lo[64]; int hi[64]; int n;
    constexpr Net9() : lo(), hi(), n(0) {
        for (int p = 1; p < 16; p <<= 1)
            for (int k = p; k >= 1; k >>= 1)
                for (int j = k % p; j + k < 16; j += 2 * k)
                    for (int i = 0; i < k; i++) {
                        int a = i + j, b = i + j + k;
                        if (b < 9 && (a / (2 * p)) == (b / (2 * p))) {
                            lo[n] = a; hi[n] = b; n++;
                        }
                    }
    }
};
__device__ constexpr Net9 N9;

template <int I>
__device__ __forceinline__ void apply9(float (&v)[9]) {
    if constexpr (I < N9.n) {
        constexpr int a = N9.lo[I];
        constexpr int b = N9.hi[I];
        float x = v[a], y = v[b];
        v[a] = fminf(x, y);
        v[b] = fmaxf(x, y);
        apply9<I + 1>(v);
    }
}
__device__ __forceinline__ void sort9(float (&v)[9]) { apply9<0>(v); }

// ---------------------------------------------------------------------------
// Merge network: 256-wire Batcher, phases p>=16 only (16-blocks pre-sorted:
// sorted column of 9 + 7x +inf pad; columns 9..15 all +inf). Exact pruning by
// constexpr always-inf simulation: b-inf -> pruned; a-inf -> MOV a<-b.
// Pad wires never read before first write. Result: wires 0..80 sorted.
// ---------------------------------------------------------------------------
struct MergeNet {
    short a[2048]; short b[2048]; short mv[2048]; int n;
    constexpr MergeNet() : a(), b(), mv(), n(0) {
        bool inf[256] = {};
        for (int c = 0; c < 16; c++)
            for (int i = 0; i < 16; i++)
                inf[c * 16 + i] = (c >= 9) || (i >= 9);
        for (int p = 16; p < 256; p <<= 1)
            for (int k = p; k >= 1; k >>= 1)
                for (int j = k % p; j + k < 256; j += 2 * k)
                    for (int i = 0; i < k; i++) {
                        int x = i + j, y = i + j + k;
                        if ((x / (2 * p)) != (y / (2 * p))) continue;
                        if (inf[y]) continue;              // no-op
                        if (inf[x]) {                       // MOV x<-y
                            a[n] = (short)x; b[n] = (short)y; mv[n] = 1; n++;
                            inf[x] = false; inf[y] = true;
                        } else {
                            a[n] = (short)x; b[n] = (short)y; mv[n] = 0; n++;
                        }
                    }
    }
};
__device__ constexpr MergeNet MN;

template <int I, int T>
__device__ __forceinline__ void mergeChunk(float (&v)[144]) {
    if constexpr (T > 0 && I < MN.n) {
        constexpr int x = MN.a[I];
        constexpr int y = MN.b[I];
        if constexpr (MN.mv[I] != 0) {
            v[x] = v[y];
        } else {
            float p = v[x], q = v[y];
            v[x] = fminf(p, q);
            v[y] = fmaxf(p, q);
        }
        mergeChunk<I + 1, T - 1>(v);
    }
}
template <int I>
__device__ __forceinline__ void mergeAll(float (&v)[144]) {
    if constexpr (I < MN.n) {
        mergeChunk<I, 32>(v);
        mergeAll<I + 32>(v);
    }
}
__device__ __forceinline__ void merge81(float (&v)[144]) { mergeAll<0>(v); }

// ---------------------------------------------------------------------------
// Pass 1: horizontal valid-window sum (9 wide). Also resets g_count.
// ---------------------------------------------------------------------------
__global__ void hsum_kernel(const float* __restrict__ pred,
                            const float* __restrict__ targ) {
    if (blockIdx.x == 0 && threadIdx.x == 0) g_count = 0u;
    int idx = blockIdx.x * 256 + threadIdx.x;
    int t   = idx >> 19;
    int pix = idx & (NPIX - 1);
    const float* __restrict__ src = t ? targ : pred;
    int w    = pix & 255;
    int base = pix - w;
    float s = 0.f;
#pragma unroll
    for (int dx = -4; dx <= 4; dx++) {
        int ww = w + dx;
        if ((unsigned)ww < 256u) s += src[base + ww];
    }
    g_tmp[t][pix] = s;
}

// ---------------------------------------------------------------------------
// Pass 2: vertical valid-window sum + divide by valid count + subtract
// ---------------------------------------------------------------------------
__global__ void vdist_kernel(const float* __restrict__ pred,
                             const float* __restrict__ targ) {
    int idx = blockIdx.x * 256 + threadIdx.x;
    int t   = idx >> 19;
    int pix = idx & (NPIX - 1);
    int w = pix & 255;
    int h = (pix >> 8) & 255;
    float s = 0.f;
#pragma unroll
    for (int dy = -4; dy <= 4; dy++) {
        int hh = h + dy;
        if ((unsigned)hh < 256u) s += g_tmp[t][pix + dy * 256];
    }
    int ch = min(h + 4, 255) - max(h - 4, 0) + 1;
    int cw = min(w + 4, 255) - max(w - 4, 0) + 1;
    const float* __restrict__ src = t ? targ : pred;
    g_dist[t][pix] = src[pix] - s / (float)(ch * cw);
}

// ---------------------------------------------------------------------------
// Main kernel: block = (batch, row, half). 256 threads: lane pair (2k,2k+1)
// = (pred, targ) of pixel w0+k. Phase 1: 272 column-sorts (9-high) published
// to interleaved SMEM. Phase 2: gather 9 sorted columns, merge network, diff
// via shfl_xor(1), reduce. Last block: fixed-order double reduction.
// ---------------------------------------------------------------------------
__global__ __launch_bounds__(256, 1) void patchcrps_kernel(float* __restrict__ out) {
    __shared__ float scol[9][280];   // interleaved: col c of tensor t at [i][2c+t]
    __shared__ float ws[8];
    __shared__ bool  isLast;

    int tid = threadIdx.x;
    int t   = tid & 1;               // 0=pred, 1=targ
    int wl  = tid >> 1;              // 0..127 pixel-in-half
    int r   = blockIdx.x & 1;
    int h   = (blockIdx.x >> 1) & 255;
    int b   = blockIdx.x >> 9;
    int w0  = r * 128;
    int ibase = b * 65536;

    const float* __restrict__ src = g_dist[t];

    // ---- 1. column sorts: thread tid -> (t, c=wl); tid<16 also c=128+wl ----
    {
        float col[9];
        int wc = w0 - 4 + wl;        // image column for this sort
        bool cv = (unsigned)wc < 256u;
#pragma unroll
        for (int i = 0; i < 9; i++) {
            int hh = h - 4 + i;
            col[i] = (cv && (unsigned)hh < 256u) ? src[ibase + hh * 256 + wc] : 0.f;
        }
        sort9(col);
#pragma unroll
        for (int i = 0; i < 9; i++) scol[i][tid] = col[i];
    }
    if (tid < 16) {
        float col[9];
        int wc = w0 + 124 + wl;      // columns 128..135
        bool cv = (unsigned)wc < 256u;
#pragma unroll
        for (int i = 0; i < 9; i++) {
            int hh = h - 4 + i;
            col[i] = (cv && (unsigned)hh < 256u) ? src[ibase + hh * 256 + wc] : 0.f;
        }
        sort9(col);
#pragma unroll
        for (int i = 0; i < 9; i++) scol[i][256 + tid] = col[i];
    }
    __syncthreads();

    // ---- 2. gather 9 sorted columns into 16-spaced wires (conflict-free) ----
    float v[144];
#pragma unroll
    for (int dx = 0; dx < 9; dx++)
#pragma unroll
        for (int i = 0; i < 9; i++)
            v[dx * 16 + i] = scol[i][tid + 2 * dx];

    // ---- 3. merge: sorted 81 ends in wires 0..80 ----
    merge81(v);

    // ---- 4. sorted diff via pair shuffle; both lanes accumulate same d^2 ----
    float acc = 0.f;
#pragma unroll
    for (int i = 0; i < 81; i++) {
        float o = __shfl_xor_sync(0xffffffffu, v[i], 1);
        float d = v[i] - o;
        acc += d * d;
    }

    // ---- 5. block reduction (deterministic) ----
#pragma unroll
    for (int off = 16; off; off >>= 1)
        acc += __shfl_xor_sync(0xffffffffu, acc, off);
    if ((tid & 31) == 0) ws[tid >> 5] = acc;
    __syncthreads();
    if (tid == 0) {
        float s = 0.f;
#pragma unroll
        for (int k = 0; k < 8; k++) s += ws[k];
        g_partial[blockIdx.x] = s;
        __threadfence();
        unsigned c = atomicAdd(&g_count, 1u);
        isLast = (c == NBLKM - 1);
    }
    __syncthreads();

    // ---- 6. fused finalize: last block, fixed-order double reduction ----
    if (isLast) {
        __shared__ double sh[256];
        double s = 0.0;
        for (int i = tid; i < NBLKM; i += 256) s += (double)g_partial[i];
        sh[tid] = s;
        __syncthreads();
        for (int off = 128; off; off >>= 1) {
            if (tid < off) sh[tid] += sh[tid + off];
            __syncthreads();
        }
        if (tid == 0) out[0] = (float)(sh[0] / (2.0 * NTOT));
    }
}

// ---------------------------------------------------------------------------
extern "C" void kernel_launch(void* const* d_in, const int* in_sizes, int n_in,
                              void* d_out, int out_size) {
    const float* pred = (const float*)d_in[0];
    const float* targ = (const float*)d_in[1];
    float* out = (float*)d_out;

    hsum_kernel<<<2 * NPIX / 256, 256>>>(pred, targ);
    vdist_kernel<<<2 * NPIX / 256, 256>>>(pred, targ);
    patchcrps_kernel<<<NBLKM, 256>>>(out);
}

// round 8
// speedup vs baseline: 7.5693x; 1.0847x over previous
#include <cuda_runtime.h>

// ---------------------------------------------------------------------------
// PatchCRPS:  mean( (sort(unfold9(pred - avg9(pred))) -
//                    sort(unfold9(targ - avg9(targ))))^2 )
// Shapes: (8,1,256,256) fp32.  K=9, P=4, count_include_pad=False.
//
// R8 = R7 with prologue SMEM fixed (8-row strips: 33KB < 48KB static limit).
//  - prologue fused into one strip kernel (8 rows/block, SMEM halo, 512 blk)
//  - main kernel exit path stripped (no fence/atomic/in-kernel finalize)
//  - lean separate deterministic finalize
// ---------------------------------------------------------------------------

#define B 8
#define H 256
#define W 256
#define NPIX (B * H * W)           // 524288
#define NBLKM (2 * B * H)          // 4096 main blocks (half-row each)
#define NTOT 42467328.0            // B*H*W*81

// Scratch (device globals — no allocation)
__device__ float g_dist[2][NPIX];      // x - avgpool9(x)
__device__ float g_partial[NBLKM];     // per-block partial sums

// ---------------------------------------------------------------------------
// Column sorter: Batcher network for n=16 pruned to 9 wires (wires>=9 = +inf).
// ---------------------------------------------------------------------------
struct Net9 {
    int lo[64]; int hi[64]; int n;
    constexpr Net9() : lo(), hi(), n(0) {
        for (int p = 1; p < 16; p <<= 1)
            for (int k = p; k >= 1; k >>= 1)
                for (int j = k % p; j + k < 16; j += 2 * k)
                    for (int i = 0; i < k; i++) {
                        int a = i + j, b = i + j + k;
                        if (b < 9 && (a / (2 * p)) == (b / (2 * p))) {
                            lo[n] = a; hi[n] = b; n++;
                        }
                    }
    }
};
__device__ constexpr Net9 N9;

template <int I>
__device__ __forceinline__ void apply9(float (&v)[9]) {
    if constexpr (I < N9.n) {
        constexpr int a = N9.lo[I];
        constexpr int b = N9.hi[I];
        float x = v[a], y = v[b];
        v[a] = fminf(x, y);
        v[b] = fmaxf(x, y);
        apply9<I + 1>(v);
    }
}
__device__ __forceinline__ void sort9(float (&v)[9]) { apply9<0>(v); }

// ---------------------------------------------------------------------------
// Merge network: 256-wire Batcher, phases p>=16 only (16-blocks pre-sorted:
// sorted column of 9 + 7x +inf pad; columns 9..15 all +inf). Exact pruning by
// constexpr always-inf simulation: b-inf -> pruned; a-inf -> MOV a<-b.
// Pad wires never read before first write. Result: wires 0..80 sorted.
// ---------------------------------------------------------------------------
struct MergeNet {
    short a[2048]; short b[2048]; short mv[2048]; int n;
    constexpr MergeNet() : a(), b(), mv(), n(0) {
        bool inf[256] = {};
        for (int c = 0; c < 16; c++)
            for (int i = 0; i < 16; i++)
                inf[c * 16 + i] = (c >= 9) || (i >= 9);
        for (int p = 16; p < 256; p <<= 1)
            for (int k = p; k >= 1; k >>= 1)
                for (int j = k % p; j + k < 256; j += 2 * k)
                    for (int i = 0; i < k; i++) {
                        int x = i + j, y = i + j + k;
                        if ((x / (2 * p)) != (y / (2 * p))) continue;
                        if (inf[y]) continue;              // no-op
                        if (inf[x]) {                       // MOV x<-y
                            a[n] = (short)x; b[n] = (short)y; mv[n] = 1; n++;
                            inf[x] = false; inf[y] = true;
                        } else {
                            a[n] = (short)x; b[n] = (short)y; mv[n] = 0; n++;
                        }
                    }
    }
};
__device__ constexpr MergeNet MN;

template <int I, int T>
__device__ __forceinline__ void mergeChunk(float (&v)[144]) {
    if constexpr (T > 0 && I < MN.n) {
        constexpr int x = MN.a[I];
        constexpr int y = MN.b[I];
        if constexpr (MN.mv[I] != 0) {
            v[x] = v[y];
        } else {
            float p = v[x], q = v[y];
            v[x] = fminf(p, q);
            v[y] = fmaxf(p, q);
        }
        mergeChunk<I + 1, T - 1>(v);
    }
}
template <int I>
__device__ __forceinline__ void mergeAll(float (&v)[144]) {
    if constexpr (I < MN.n) {
        mergeChunk<I, 32>(v);
        mergeAll<I + 32>(v);
    }
}
__device__ __forceinline__ void merge81(float (&v)[144]) { mergeAll<0>(v); }

// ---------------------------------------------------------------------------
// Fused prologue: block = (tensor, batch, 8-row strip). Loads 16 rows (with
// clamped halo) into SMEM, computes 16 rows of horizontal 9-sums in SMEM,
// then 8 rows of  dist = x - boxsum/validcount  straight to g_dist.
// SMEM: 16*264*4 + 16*256*4 = 33 KB.  Grid = 2*8*32 = 512 blocks.
// ---------------------------------------------------------------------------
__global__ __launch_bounds__(256) void prologue_kernel(
        const float* __restrict__ pred, const float* __restrict__ targ) {
    __shared__ float raw[16][264];   // 4 zero pad each side
    __shared__ float hs[16][256];    // horizontal 9-sums

    int tid = threadIdx.x;
    int t   = blockIdx.x >> 8;
    int b   = (blockIdx.x >> 5) & 7;
    int s   = blockIdx.x & 31;
    int r0  = s * 8;
    const float* __restrict__ src = t ? targ : pred;
    int ibase = b * 65536;

    // load 16 rows (r0-4 .. r0+11), zero outside image; zero side pads
#pragma unroll
    for (int r = 0; r < 16; r++) {
        int gr = r0 - 4 + r;
        raw[r][tid + 4] = ((unsigned)gr < 256u) ? src[ibase + gr * 256 + tid] : 0.f;
    }
    if (tid < 4) {
#pragma unroll
        for (int r = 0; r < 16; r++) { raw[r][tid] = 0.f; raw[r][260 + tid] = 0.f; }
    }
    __syncthreads();

    // horizontal 9-sums for all 16 rows (thread = column)
#pragma unroll
    for (int r = 0; r < 16; r++) {
        float a = 0.f;
#pragma unroll
        for (int i = 0; i < 9; i++) a += raw[r][tid + i];
        hs[r][tid] = a;
    }
    __syncthreads();

    // 8 output rows
    int cw = min(tid + 4, 255) - max(tid - 4, 0) + 1;
#pragma unroll
    for (int k = 0; k < 8; k++) {
        int h  = r0 + k;
        int lr = k + 4;
        float vs = 0.f;
#pragma unroll
        for (int j = -4; j <= 4; j++) vs += hs[lr + j][tid];
        int ch = min(h + 4, 255) - max(h - 4, 0) + 1;
        g_dist[t][ibase + h * 256 + tid] = raw[lr][tid + 4] - vs / (float)(ch * cw);
    }
}

// ---------------------------------------------------------------------------
// Main kernel: block = (batch, row, half). 256 threads: lane pair (2k,2k+1)
// = (pred, targ) of pixel w0+k. Phase 1: 272 column-sorts (9-high) published
// to interleaved SMEM. Phase 2: gather 9 sorted columns, merge network, diff
// via shfl_xor(1), block-reduce, store partial. No fence/atomic tail.
// ---------------------------------------------------------------------------
__global__ __launch_bounds__(256, 1) void patchcrps_kernel() {
    __shared__ float scol[9][280];   // interleaved: col c of tensor t at [i][2c+t]
    __shared__ float ws[8];

    int tid = threadIdx.x;
    int t   = tid & 1;               // 0=pred, 1=targ
    int wl  = tid >> 1;              // 0..127 pixel-in-half
    int r   = blockIdx.x & 1;
    int h   = (blockIdx.x >> 1) & 255;
    int b   = blockIdx.x >> 9;
    int w0  = r * 128;
    int ibase = b * 65536;

    const float* __restrict__ src = g_dist[t];

    // ---- 1. column sorts: thread tid -> (t, c=wl); tid<16 also c=128+wl ----
    {
        float col[9];
        int wc = w0 - 4 + wl;
        bool cv = (unsigned)wc < 256u;
#pragma unroll
        for (int i = 0; i < 9; i++) {
            int hh = h - 4 + i;
            col[i] = (cv && (unsigned)hh < 256u) ? src[ibase + hh * 256 + wc] : 0.f;
        }
        sort9(col);
#pragma unroll
        for (int i = 0; i < 9; i++) scol[i][tid] = col[i];
    }
    if (tid < 16) {
        float col[9];
        int wc = w0 + 124 + wl;      // columns w0+124..w0+131
        bool cv = (unsigned)wc < 256u;
#pragma unroll
        for (int i = 0; i < 9; i++) {
            int hh = h - 4 + i;
            col[i] = (cv && (unsigned)hh < 256u) ? src[ibase + hh * 256 + wc] : 0.f;
        }
        sort9(col);
#pragma unroll
        for (int i = 0; i < 9; i++) scol[i][256 + tid] = col[i];
    }
    __syncthreads();

    // ---- 2. gather 9 sorted columns into 16-spaced wires (conflict-free) ----
    float v[144];
#pragma unroll
    for (int dx = 0; dx < 9; dx++)
#pragma unroll
        for (int i = 0; i < 9; i++)
            v[dx * 16 + i] = scol[i][tid + 2 * dx];

    // ---- 3. merge: sorted 81 ends in wires 0..80 ----
    merge81(v);

    // ---- 4. sorted diff via pair shuffle; both lanes accumulate same d^2 ----
    float acc = 0.f;
#pragma unroll
    for (int i = 0; i < 81; i++) {
        float o = __shfl_xor_sync(0xffffffffu, v[i], 1);
        float d = v[i] - o;
        acc += d * d;
    }

    // ---- 5. block reduction (deterministic) + partial store; exit ----
#pragma unroll
    for (int off = 16; off; off >>= 1)
        acc += __shfl_xor_sync(0xffffffffu, acc, off);
    if ((tid & 31) == 0) ws[tid >> 5] = acc;
    __syncthreads();
    if (tid == 0) {
        float s = 0.f;
#pragma unroll
        for (int k = 0; k < 8; k++) s += ws[k];
        g_partial[blockIdx.x] = s;
    }
}

// ---------------------------------------------------------------------------
// Finalize: fixed-order double reduction of 4096 partials (1 block).
// ---------------------------------------------------------------------------
__global__ __launch_bounds__(512) void finalize_kernel(float* __restrict__ out) {
    __shared__ double sh[512];
    int tid = threadIdx.x;
    double s = 0.0;
#pragma unroll
    for (int e = 0; e < 8; e++) s += (double)g_partial[tid * 8 + e];
    sh[tid] = s;
    __syncthreads();
    for (int off = 256; off; off >>= 1) {
        if (tid < off) sh[tid] += sh[tid + off];
        __syncthreads();
    }
    if (tid == 0) out[0] = (float)(sh[0] / (2.0 * NTOT));
}

// ---------------------------------------------------------------------------
extern "C" void kernel_launch(void* const* d_in, const int* in_sizes, int n_in,
                              void* d_out, int out_size) {
    const float* pred = (const float*)d_in[0];
    const float* targ = (const float*)d_in[1];
    float* out = (float*)d_out;

    prologue_kernel<<<512, 256>>>(pred, targ);
    patchcrps_kernel<<<NBLKM, 256>>>();
    finalize_kernel<<<1, 512>>>(out);
}

// round 9
// speedup vs baseline: 8.4370x; 1.1146x over previous
#include <cuda_runtime.h>

// ---------------------------------------------------------------------------
// PatchCRPS:  mean( (sort(unfold9(pred - avg9(pred))) -
//                    sort(unfold9(targ - avg9(targ))))^2 )
// Shapes: (8,1,256,256) fp32.  K=9, P=4, count_include_pad=False.
//
// R9 = R8 + dual-pipe compare-exchange: 2/7 of merge CEs computed on the fma
// pipe via  min,max = (p+q)/2 -/+ |p-q|/2  (5 fma ops, 0 alu ops), the rest
// stay FMNMX (2 alu ops).  alu/fma issue load balanced -> CE stream ~0.71x.
// ---------------------------------------------------------------------------

#define B 8
#define H 256
#define W 256
#define NPIX (B * H * W)           // 524288
#define NBLKM (2 * B * H)          // 4096 main blocks (half-row each)
#define NTOT 42467328.0            // B*H*W*81

// Scratch (device globals — no allocation)
__device__ float g_dist[2][NPIX];      // x - avgpool9(x)
__device__ float g_partial[NBLKM];     // per-block partial sums

// ---------------------------------------------------------------------------
// Column sorter: Batcher network for n=16 pruned to 9 wires (wires>=9 = +inf).
// ---------------------------------------------------------------------------
struct Net9 {
    int lo[64]; int hi[64]; int n;
    constexpr Net9() : lo(), hi(), n(0) {
        for (int p = 1; p < 16; p <<= 1)
            for (int k = p; k >= 1; k >>= 1)
                for (int j = k % p; j + k < 16; j += 2 * k)
                    for (int i = 0; i < k; i++) {
                        int a = i + j, b = i + j + k;
                        if (b < 9 && (a / (2 * p)) == (b / (2 * p))) {
                            lo[n] = a; hi[n] = b; n++;
                        }
                    }
    }
};
__device__ constexpr Net9 N9;

template <int I>
__device__ __forceinline__ void apply9(float (&v)[9]) {
    if constexpr (I < N9.n) {
        constexpr int a = N9.lo[I];
        constexpr int b = N9.hi[I];
        float x = v[a], y = v[b];
        v[a] = fminf(x, y);
        v[b] = fmaxf(x, y);
        apply9<I + 1>(v);
    }
}
__device__ __forceinline__ void sort9(float (&v)[9]) { apply9<0>(v); }

// ---------------------------------------------------------------------------
// Merge network: 256-wire Batcher, phases p>=16 only (16-blocks pre-sorted:
// sorted column of 9 + 7x +inf pad; columns 9..15 all +inf). Exact pruning by
// constexpr always-inf simulation: b-inf -> pruned; a-inf -> MOV a<-b.
// Pad wires never read before first write. Result: wires 0..80 sorted.
// ---------------------------------------------------------------------------
struct MergeNet {
    short a[2048]; short b[2048]; short mv[2048]; int n;
    constexpr MergeNet() : a(), b(), mv(), n(0) {
        bool inf[256] = {};
        for (int c = 0; c < 16; c++)
            for (int i = 0; i < 16; i++)
                inf[c * 16 + i] = (c >= 9) || (i >= 9);
        for (int p = 16; p < 256; p <<= 1)
            for (int k = p; k >= 1; k >>= 1)
                for (int j = k % p; j + k < 256; j += 2 * k)
                    for (int i = 0; i < k; i++) {
                        int x = i + j, y = i + j + k;
                        if ((x / (2 * p)) != (y / (2 * p))) continue;
                        if (inf[y]) continue;              // no-op
                        if (inf[x]) {                       // MOV x<-y
                            a[n] = (short)x; b[n] = (short)y; mv[n] = 1; n++;
                            inf[x] = false; inf[y] = true;
                        } else {
                            a[n] = (short)x; b[n] = (short)y; mv[n] = 0; n++;
                        }
                    }
    }
};
__device__ constexpr MergeNet MN;

template <int I, int T>
__device__ __forceinline__ void mergeChunk(float (&v)[144]) {
    if constexpr (T > 0 && I < MN.n) {
        constexpr int x = MN.a[I];
        constexpr int y = MN.b[I];
        if constexpr (MN.mv[I] != 0) {
            v[x] = v[y];
        } else if constexpr ((I % 7) < 2) {
            // fma-pipe CE: min,max = (p+q)/2 -/+ |p-q|/2
            float p = v[x], q = v[y];
            float d  = p - q;                  // FADD
            float hd = d * 0.5f;               // FMUL
            float hs = __fmaf_rn(d, 0.5f, q);  // FFMA  = (p+q)/2
            float ad = fabsf(hd);              // folds into operand |.|
            v[x] = hs - ad;                    // FADD
            v[y] = hs + ad;                    // FADD
        } else {
            // alu-pipe CE
            float p = v[x], q = v[y];
            v[x] = fminf(p, q);
            v[y] = fmaxf(p, q);
        }
        mergeChunk<I + 1, T - 1>(v);
    }
}
template <int I>
__device__ __forceinline__ void mergeAll(float (&v)[144]) {
    if constexpr (I < MN.n) {
        mergeChunk<I, 32>(v);
        mergeAll<I + 32>(v);
    }
}
__device__ __forceinline__ void merge81(float (&v)[144]) { mergeAll<0>(v); }

// ---------------------------------------------------------------------------
// Fused prologue: block = (tensor, batch, 8-row strip). Loads 16 rows (with
// halo) into SMEM, 16 rows of horizontal 9-sums, then 8 rows of
// dist = x - boxsum/validcount straight to g_dist. 33 KB SMEM, 512 blocks.
// ---------------------------------------------------------------------------
__global__ __launch_bounds__(256) void prologue_kernel(
        const float* __restrict__ pred, const float* __restrict__ targ) {
    __shared__ float raw[16][264];   // 4 zero pad each side
    __shared__ float hs[16][256];    // horizontal 9-sums

    int tid = threadIdx.x;
    int t   = blockIdx.x >> 8;
    int b   = (blockIdx.x >> 5) & 7;
    int s   = blockIdx.x & 31;
    int r0  = s * 8;
    const float* __restrict__ src = t ? targ : pred;
    int ibase = b * 65536;

#pragma unroll
    for (int r = 0; r < 16; r++) {
        int gr = r0 - 4 + r;
        raw[r][tid + 4] = ((unsigned)gr < 256u) ? src[ibase + gr * 256 + tid] : 0.f;
    }
    if (tid < 4) {
#pragma unroll
        for (int r = 0; r < 16; r++) { raw[r][tid] = 0.f; raw[r][260 + tid] = 0.f; }
    }
    __syncthreads();

#pragma unroll
    for (int r = 0; r < 16; r++) {
        float a = 0.f;
#pragma unroll
        for (int i = 0; i < 9; i++) a += raw[r][tid + i];
        hs[r][tid] = a;
    }
    __syncthreads();

    int cw = min(tid + 4, 255) - max(tid - 4, 0) + 1;
#pragma unroll
    for (int k = 0; k < 8; k++) {
        int h  = r0 + k;
        int lr = k + 4;
        float vs = 0.f;
#pragma unroll
        for (int j = -4; j <= 4; j++) vs += hs[lr + j][tid];
        int ch = min(h + 4, 255) - max(h - 4, 0) + 1;
        g_dist[t][ibase + h * 256 + tid] = raw[lr][tid + 4] - vs / (float)(ch * cw);
    }
}

// ---------------------------------------------------------------------------
// Main kernel: block = (batch, row, half). 256 threads: lane pair (2k,2k+1)
// = (pred, targ) of pixel w0+k. Column sorts -> interleaved SMEM -> gather 9
// sorted columns -> merge network -> diff via shfl_xor(1) -> partial store.
// ---------------------------------------------------------------------------
__global__ __launch_bounds__(256, 1) void patchcrps_kernel() {
    __shared__ float scol[9][280];   // interleaved: col c of tensor t at [i][2c+t]
    __shared__ float ws[8];

    int tid = threadIdx.x;
    int t   = tid & 1;               // 0=pred, 1=targ
    int wl  = tid >> 1;              // 0..127 pixel-in-half
    int r   = blockIdx.x & 1;
    int h   = (blockIdx.x >> 1) & 255;
    int b   = blockIdx.x >> 9;
    int w0  = r * 128;
    int ibase = b * 65536;

    const float* __restrict__ src = g_dist[t];

    // ---- 1. column sorts: thread tid -> (t, c=wl); tid<16 also c=128+wl ----
    {
        float col[9];
        int wc = w0 - 4 + wl;
        bool cv = (unsigned)wc < 256u;
#pragma unroll
        for (int i = 0; i < 9; i++) {
            int hh = h - 4 + i;
            col[i] = (cv && (unsigned)hh < 256u) ? src[ibase + hh * 256 + wc] : 0.f;
        }
        sort9(col);
#pragma unroll
        for (int i = 0; i < 9; i++) scol[i][tid] = col[i];
    }
    if (tid < 16) {
        float col[9];
        int wc = w0 + 124 + wl;      // columns w0+124..w0+131
        bool cv = (unsigned)wc < 256u;
#pragma unroll
        for (int i = 0; i < 9; i++) {
            int hh = h - 4 + i;
            col[i] = (cv && (unsigned)hh < 256u) ? src[ibase + hh * 256 + wc] : 0.f;
        }
        sort9(col);
#pragma unroll
        for (int i = 0; i < 9; i++) scol[i][256 + tid] = col[i];
    }
    __syncthreads();

    // ---- 2. gather 9 sorted columns into 16-spaced wires (conflict-free) ----
    float v[144];
#pragma unroll
    for (int dx = 0; dx < 9; dx++)
#pragma unroll
        for (int i = 0; i < 9; i++)
            v[dx * 16 + i] = scol[i][tid + 2 * dx];

    // ---- 3. merge: sorted 81 ends in wires 0..80 ----
    merge81(v);

    // ---- 4. sorted diff via pair shuffle; both lanes accumulate same d^2 ----
    float acc = 0.f;
#pragma unroll
    for (int i = 0; i < 81; i++) {
        float o = __shfl_xor_sync(0xffffffffu, v[i], 1);
        float d = v[i] - o;
        acc += d * d;
    }

    // ---- 5. block reduction (deterministic) + partial store; exit ----
#pragma unroll
    for (int off = 16; off; off >>= 1)
        acc += __shfl_xor_sync(0xffffffffu, acc, off);
    if ((tid & 31) == 0) ws[tid >> 5] = acc;
    __syncthreads();
    if (tid == 0) {
        float s = 0.f;
#pragma unroll
        for (int k = 0; k < 8; k++) s += ws[k];
        g_partial[blockIdx.x] = s;
    }
}

// ---------------------------------------------------------------------------
// Finalize: fixed-order double reduction of 4096 partials (1 block).
// ---------------------------------------------------------------------------
__global__ __launch_bounds__(512) void finalize_kernel(float* __restrict__ out) {
    __shared__ double sh[512];
    int tid = threadIdx.x;
    double s = 0.0;
#pragma unroll
    for (int e = 0; e < 8; e++) s += (double)g_partial[tid * 8 + e];
    sh[tid] = s;
    __syncthreads();
    for (int off = 256; off; off >>= 1) {
        if (tid < off) sh[tid] += sh[tid + off];
        __syncthreads();
    }
    if (tid == 0) out[0] = (float)(sh[0] / (2.0 * NTOT));
}

// ---------------------------------------------------------------------------
extern "C" void kernel_launch(void* const* d_in, const int* in_sizes, int n_in,
                              void* d_out, int out_size) {
    const float* pred = (const float*)d_in[0];
    const float* targ = (const float*)d_in[1];
    float* out = (float*)d_out;

    prologue_kernel<<<512, 256>>>(pred, targ);
    patchcrps_kernel<<<NBLKM, 256>>>();
    finalize_kernel<<<1, 512>>>(out);
}